// round 14
// baseline (speedup 1.0000x reference)
#include <cuda_runtime.h>
#include <cstdint>

#define CC 256
#define BB 1024
typedef unsigned long long ull;

// Round-robin tournament over 8 channel-tiles: rounds 0..6 = perfect matchings
// (every unordered tile-pair exactly once); rounds 7,8 = diagonal tiles.
__constant__ int c_I[9][4] = {
    {7,1,2,3},{7,2,3,4},{7,3,4,5},{7,4,5,6},{7,5,6,0},{7,6,0,1},{7,0,1,2},
    {0,1,2,3},{4,5,6,7}};
__constant__ int c_J[9][4] = {
    {0,6,5,4},{1,0,6,5},{2,1,0,6},{3,2,1,0},{4,3,2,1},{5,4,3,2},{6,5,4,3},
    {0,1,2,3},{4,5,6,7}};

// Pre-ROTATED W tiles: g_Wrot[((rnd*4+k)*1024) + s*32 + cx]
//   = W[J*32 + ((cx+s)&31)][I*32 + cx],  W symmetric from w3, diag 0.
__device__ float g_Wrot[9 * 4 * 1024];

// Per-round conflict-free scratch: g_scratch[rnd][rp][c] holds the packed
// (row 2rp, row 2rp+1) partial for channel c from round rnd. Within a round
// every channel-tile appears exactly once across the 4 (I,J) passes -> each
// slot has exactly ONE writer (plain STG.64, no atomics, no zeroing).
__device__ ull g_scratch[9 * 512 * 256];

__global__ void build_Wrot_kernel(const float* __restrict__ w3) {
    int idx = blockIdx.x * blockDim.x + threadIdx.x;
    if (idx >= 9 * 4 * 1024) return;
    int rnd = idx >> 12;
    int rem = idx & 4095;
    int k   = rem >> 10;
    int s   = (rem >> 5) & 31;
    int cx  = rem & 31;
    int I = c_I[rnd][k], J = c_J[rnd][k];
    int c = I * 32 + cx;
    int j = J * 32 + ((cx + s) & 31);
    float v = 0.0f;
    if (j != c) {
        int p = j < c ? j : c;
        int q = j < c ? c : j;
        int e = p * (2 * CC - p - 1) / 2 + (q - p - 1);  // np.triu_indices(CC,1)
        v = w3[e];
    }
    g_Wrot[idx] = v;
}

// ---- packed f32x2 helpers (sm_100a) ----
__device__ __forceinline__ ull pk2(float lo, float hi) {
    ull r;
    asm("mov.b64 %0, {%1, %2};" : "=l"(r) : "f"(lo), "f"(hi));
    return r;
}
__device__ __forceinline__ void upk2(ull v, float& lo, float& hi) {
    asm("mov.b64 {%0, %1}, %2;" : "=f"(lo), "=f"(hi) : "l"(v));
}
__device__ __forceinline__ ull add2(ull a, ull b) {
    ull r;
    asm("add.rn.f32x2 %0, %1, %2;" : "=l"(r) : "l"(a), "l"(b));
    return r;
}
__device__ __forceinline__ ull mul2(ull a, ull b) {
    ull r;
    asm("mul.rn.f32x2 %0, %1, %2;" : "=l"(r) : "l"(a), "l"(b));
    return r;
}
__device__ __forceinline__ ull fma2_(ull a, ull b, ull c) {
    ull r;
    asm("fma.rn.f32x2 %0, %1, %2, %3;" : "=l"(r) : "l"(a), "l"(b), "l"(c));
    return r;
}

// v(c,j) = u(|d|)*(x_j-x_c)*W[j,c] is antisymmetric; each unordered pair computed once.
// Row sums -> accI; column sums -> four lane-rotating accumulators (shfl-by-4 per
// 4 steps, acc_r fixed up by content-up-by-r). Results land in g_scratch via ONE
// packed STG.64 per side (the old REDG atomics were ~60% of LSU occupancy).
__global__ __launch_bounds__(256, 4) void son_main_kernel(
    const float* __restrict__ x, const float* __restrict__ w1,
    const float* __restrict__ w2)
{
    __shared__ float  Wr[4][1024];     // 16 KB: Wr[k][s*32+cx], pre-rotated
    __shared__ float2 xd[8][8][64];    // 32 KB: xd[p][T][i] = x-pair for ch T*32+(i&31), dup'd

    const int tid  = threadIdx.x;
    const int wrp  = tid >> 5;         // row-pair within group (0..7)
    const int cx   = tid & 31;
    const int rg   = blockIdx.x;       // 0..63
    const int rnd  = blockIdx.y;       // 0..8
    const int rowb = rg * 16;
    const int rp   = rg * 8 + wrp;     // global row-pair 0..511

    // Stage x rows, duplicated within each 32-channel tile (coalesced reads)
    {
        float w1s = w1[tid];
        int T = tid >> 5, ci = tid & 31;
#pragma unroll
        for (int p = 0; p < 8; p++) {
            float lo = x[(rowb + 2 * p) * CC + tid] * w1s;
            float hi = x[(rowb + 2 * p + 1) * CC + tid] * w1s;
            float2 v = make_float2(lo, hi);
            xd[p][T][ci]      = v;
            xd[p][T][ci + 32] = v;
        }
    }
    // Stage the round's 4 rotated W tiles: 1024 float4, linear & coalesced
    {
        const float4* src = reinterpret_cast<const float4*>(g_Wrot + rnd * 4096);
        float4* dst = reinterpret_cast<float4*>(&Wr[0][0]);
#pragma unroll
        for (int m = 0; m < 4; m++)
            dst[tid + m * 256] = __ldg(src + tid + m * 256);
    }
    __syncthreads();

    const float s0 = 0.505f * w2[0], s1 = 0.505f * w2[1];
    const float s2 = 0.505f * w2[2], s3 = 0.505f * w2[3];
    const ull C0 = pk2(s0, s0), C1 = pk2(s1, s1);
    const ull C2 = pk2(s2, s2), C3 = pk2(s3, s3);
    const float kf = 0.495f / 0.505f;
    const ull K = pk2(kf, kf);

    const bool diag = (rnd >= 7);
    ull* scr = g_scratch + (rnd * 512 + rp) * 256;   // this warp's conflict-free slice

#pragma unroll 1
    for (int k = 0; k < 4; k++) {
        const int I = c_I[rnd][k], J = c_J[rnd][k];
        const ull nxc = (*reinterpret_cast<const ull*>(&xd[wrp][I][cx])) ^ 0x8000000080000000ULL;
        const ull*   xb = reinterpret_cast<const ull*>(&xd[wrp][J][cx]);  // xb[s]: immediate
        const float* Wb = &Wr[k][cx];                                     // Wb[s*32]: immediate

        if (!diag) {
            ull accI = 0ULL;
            ull accJ[4] = {0ULL, 0ULL, 0ULL, 0ULL};
#pragma unroll
            for (int g = 0; g < 8; g++) {
#pragma unroll
                for (int r = 0; r < 4; r++) {
                    const int s = 4 * g + r;
                    float w = Wb[s * 32];
                    ull xj  = xb[s];
                    ull wpk = pk2(w, w);
                    ull d = add2(xj, nxc);
                    ull a = d & 0x7fffffff7fffffffULL;
                    ull t = fma2_(C3, a, C2);
                    t = fma2_(t, a, C1);
                    t = fma2_(t, a, C0);
                    ull u = fma2_(K, t & 0x7fffffff7fffffffULL, t);
                    ull m = mul2(d, wpk);
                    accI    = fma2_(u, m, accI);
                    accJ[r] = fma2_(u, m, accJ[r]);
                }
#pragma unroll
                for (int r = 0; r < 4; r++)
                    accJ[r] = __shfl_sync(0xffffffffu, accJ[r], (cx + 4) & 31);
            }
            // fix-ups: acc_r over-rotated by r -> move content up by r
            accJ[1] = __shfl_sync(0xffffffffu, accJ[1], (cx + 31) & 31);
            accJ[2] = __shfl_sync(0xffffffffu, accJ[2], (cx + 30) & 31);
            accJ[3] = __shfl_sync(0xffffffffu, accJ[3], (cx + 29) & 31);

            ull negJ = add2(add2(accJ[0], accJ[1]), add2(accJ[2], accJ[3]))
                       ^ 0x8000000080000000ULL;                       // v(j,c) = -v(c,j)
            scr[I * 32 + cx] = accI;   // single writer per slot: plain STG.64
            scr[J * 32 + cx] = negJ;
        } else {
            ull accI = 0ULL;
#pragma unroll
            for (int s = 0; s < 32; s++) {
                float w = Wb[s * 32];
                ull xj  = xb[s];
                ull wpk = pk2(w, w);
                ull d = add2(xj, nxc);
                ull a = d & 0x7fffffff7fffffffULL;
                ull t = fma2_(C3, a, C2);
                t = fma2_(t, a, C1);
                t = fma2_(t, a, C0);
                ull u = fma2_(K, t & 0x7fffffff7fffffffULL, t);
                accI = fma2_(u, mul2(d, wpk), accI);
            }
            scr[I * 32 + cx] = accI;
        }
    }
}

// Sum the 8 relevant round-slices per element and scatter to [row][c] layout.
// Channel c belongs to tile c>>5: rounds 0..6 always contribute; the diagonal
// contribution is round 7 for tiles 0-3 (c<128), round 8 for tiles 4-7.
__global__ __launch_bounds__(256) void sum_kernel(float* __restrict__ out) {
    const int c  = threadIdx.x;
    const int rp = blockIdx.x;        // 0..511
    const ull* base = g_scratch + rp * 256 + c;
    ull acc = base[0 * 512 * 256];
#pragma unroll
    for (int r = 1; r < 7; r++)
        acc = add2(acc, base[r * 512 * 256]);
    const int last = (c < 128) ? 7 : 8;
    acc = add2(acc, base[last * 512 * 256]);
    float lo, hi;
    upk2(acc, lo, hi);
    out[(2 * rp) * CC + c]     = lo;
    out[(2 * rp + 1) * CC + c] = hi;
}

extern "C" void kernel_launch(void* const* d_in, const int* in_sizes, int n_in,
                              void* d_out, int out_size) {
    // Identify inputs by element count (robust to ordering):
    // x: 262144, w1: 256, w2: 4, w3: 32640, diff_indices: 8355840 (unused)
    const float* x = nullptr;
    const float* w1 = nullptr;
    const float* w2 = nullptr;
    const float* w3 = nullptr;
    for (int i = 0; i < n_in; i++) {
        switch (in_sizes[i]) {
            case BB * CC:            x  = (const float*)d_in[i]; break;
            case CC:                 w1 = (const float*)d_in[i]; break;
            case 4:                  w2 = (const float*)d_in[i]; break;
            case CC * (CC - 1) / 2:  w3 = (const float*)d_in[i]; break;
            default: break;  // diff_indices not needed
        }
    }

    build_Wrot_kernel<<<(9 * 4 * 1024 + 255) / 256, 256>>>(w3);
    dim3 grid(BB / 16, 9);     // 64 row-groups x 9 rounds = 576 blocks (one wave @ 4/SM)
    son_main_kernel<<<grid, 256>>>(x, w1, w2);
    sum_kernel<<<512, 256>>>((float*)d_out);
}

// round 15
// speedup vs baseline: 1.0468x; 1.0468x over previous
#include <cuda_runtime.h>
#include <cstdint>

#define CC 256
#define BB 1024
typedef unsigned long long ull;

// Round-robin tournament over 8 channel-tiles: rounds 0..6 = perfect matchings
// (every unordered tile-pair exactly once); rounds 7,8 = diagonal tiles.
__constant__ int c_I[9][4] = {
    {7,1,2,3},{7,2,3,4},{7,3,4,5},{7,4,5,6},{7,5,6,0},{7,6,0,1},{7,0,1,2},
    {0,1,2,3},{4,5,6,7}};
__constant__ int c_J[9][4] = {
    {0,6,5,4},{1,0,6,5},{2,1,0,6},{3,2,1,0},{4,3,2,1},{5,4,3,2},{6,5,4,3},
    {0,1,2,3},{4,5,6,7}};

// ---- packed f32x2 helpers (sm_100a) ----
__device__ __forceinline__ ull pk2(float lo, float hi) {
    ull r;
    asm("mov.b64 %0, {%1, %2};" : "=l"(r) : "f"(lo), "f"(hi));
    return r;
}
__device__ __forceinline__ void upk2(ull v, float& lo, float& hi) {
    asm("mov.b64 {%0, %1}, %2;" : "=f"(lo), "=f"(hi) : "l"(v));
}
__device__ __forceinline__ ull add2(ull a, ull b) {
    ull r;
    asm("add.rn.f32x2 %0, %1, %2;" : "=l"(r) : "l"(a), "l"(b));
    return r;
}
__device__ __forceinline__ ull mul2(ull a, ull b) {
    ull r;
    asm("mul.rn.f32x2 %0, %1, %2;" : "=l"(r) : "l"(a), "l"(b));
    return r;
}
__device__ __forceinline__ ull fma2_(ull a, ull b, ull c) {
    ull r;
    asm("fma.rn.f32x2 %0, %1, %2, %3;" : "=l"(r) : "l"(a), "l"(b), "l"(c));
    return r;
}
__device__ __forceinline__ void red_add(float* p, float v) {
    asm volatile("red.global.add.f32 [%0], %1;" :: "l"(p), "f"(v) : "memory");
}

// v(c,j) = u(|d|)*(x_j-x_c)*W[j,c] is antisymmetric; each unordered pair computed once.
// Row sums -> accI; column sums -> four lane-rotating accumulators (shfl-by-4 per
// 4 steps; acc_r fixed up by content-up-by-r). This version computes its 4
// pre-rotated W tiles DIRECTLY from w3 in the prologue (no build kernel: any
// extra kernel node costs 3-4.5us of pure launch overhead at this scale).
__global__ __launch_bounds__(256, 4) void son_main_kernel(
    const float* __restrict__ x, const float* __restrict__ w1,
    const float* __restrict__ w2, const float* __restrict__ w3,
    float* __restrict__ out)
{
    __shared__ float  Wr[4][1024];     // 16 KB: Wr[k][s*32+cx], pre-rotated on the fly
    __shared__ float2 xd[8][8][64];    // 32 KB: xd[p][T][i] = x-pair for ch T*32+(i&31), dup'd

    const int tid  = threadIdx.x;
    const int wrp  = tid >> 5;         // row-pair within group (0..7)
    const int cx   = tid & 31;
    const int rg   = blockIdx.x;       // 0..63
    const int rnd  = blockIdx.y;       // 0..8
    const int rowb = rg * 16;

    // Stage x rows, duplicated within each 32-channel tile (coalesced reads)
    {
        float w1s = w1[tid];
        int T = tid >> 5, ci = tid & 31;
#pragma unroll
        for (int p = 0; p < 8; p++) {
            float lo = x[(rowb + 2 * p) * CC + tid] * w1s;
            float hi = x[(rowb + 2 * p + 1) * CC + tid] * w1s;
            float2 v = make_float2(lo, hi);
            xd[p][T][ci]      = v;
            xd[p][T][ci + 32] = v;
        }
    }
    // Stage the round's 4 rotated W tiles straight from w3:
    // Wr[k][s*32+cxe] = W[J*32+((cxe+s)&31)][I*32+cxe], W symmetric, diag 0.
#pragma unroll
    for (int k = 0; k < 4; k++) {
        const int I = c_I[rnd][k], J = c_J[rnd][k];
#pragma unroll
        for (int m = 0; m < 4; m++) {
            int entry = tid + m * 256;          // 0..1023
            int s   = entry >> 5;
            int cxe = entry & 31;
            int c = I * 32 + cxe;
            int j = J * 32 + ((cxe + s) & 31);
            float v = 0.0f;
            if (j != c) {
                int p = j < c ? j : c;
                int q = j < c ? c : j;
                int e = p * (2 * CC - p - 1) / 2 + (q - p - 1);  // np.triu_indices(CC,1)
                v = __ldg(w3 + e);              // 128 KB, L2-resident
            }
            Wr[k][entry] = v;
        }
    }
    __syncthreads();

    const float s0 = 0.505f * w2[0], s1 = 0.505f * w2[1];
    const float s2 = 0.505f * w2[2], s3 = 0.505f * w2[3];
    const ull C0 = pk2(s0, s0), C1 = pk2(s1, s1);
    const ull C2 = pk2(s2, s2), C3 = pk2(s3, s3);
    const float kf = 0.495f / 0.505f;
    const ull K = pk2(kf, kf);

    const bool diag = (rnd >= 7);
    float* outr0 = out + (rowb + 2 * wrp) * CC;
    float* outr1 = outr0 + CC;

#pragma unroll 1
    for (int k = 0; k < 4; k++) {
        const int I = c_I[rnd][k], J = c_J[rnd][k];
        const ull nxc = (*reinterpret_cast<const ull*>(&xd[wrp][I][cx])) ^ 0x8000000080000000ULL;
        const ull*   xb = reinterpret_cast<const ull*>(&xd[wrp][J][cx]);  // xb[s]: immediate
        const float* Wb = &Wr[k][cx];                                     // Wb[s*32]: immediate
        float lo, hi;

        if (!diag) {
            ull accI = 0ULL;
            ull accJ[4] = {0ULL, 0ULL, 0ULL, 0ULL};
#pragma unroll
            for (int g = 0; g < 8; g++) {
#pragma unroll
                for (int r = 0; r < 4; r++) {
                    const int s = 4 * g + r;
                    float w = Wb[s * 32];
                    ull xj  = xb[s];
                    ull wpk = pk2(w, w);
                    ull d = add2(xj, nxc);
                    ull a = d & 0x7fffffff7fffffffULL;
                    ull t = fma2_(C3, a, C2);
                    t = fma2_(t, a, C1);
                    t = fma2_(t, a, C0);
                    ull u = fma2_(K, t & 0x7fffffff7fffffffULL, t);
                    ull m = mul2(d, wpk);
                    accI    = fma2_(u, m, accI);
                    accJ[r] = fma2_(u, m, accJ[r]);
                }
#pragma unroll
                for (int r = 0; r < 4; r++)
                    accJ[r] = __shfl_sync(0xffffffffu, accJ[r], (cx + 4) & 31);
            }
            // fix-ups: acc_r over-rotated by r -> move content up by r
            accJ[1] = __shfl_sync(0xffffffffu, accJ[1], (cx + 31) & 31);
            accJ[2] = __shfl_sync(0xffffffffu, accJ[2], (cx + 30) & 31);
            accJ[3] = __shfl_sync(0xffffffffu, accJ[3], (cx + 29) & 31);

            upk2(accI, lo, hi);
            red_add(outr0 + I * 32 + cx, lo);
            red_add(outr1 + I * 32 + cx, hi);
            ull negJ = add2(add2(accJ[0], accJ[1]), add2(accJ[2], accJ[3]))
                       ^ 0x8000000080000000ULL;                       // v(j,c) = -v(c,j)
            upk2(negJ, lo, hi);
            red_add(outr0 + J * 32 + cx, lo);
            red_add(outr1 + J * 32 + cx, hi);
        } else {
            ull accI = 0ULL;
#pragma unroll
            for (int s = 0; s < 32; s++) {
                float w = Wb[s * 32];
                ull xj  = xb[s];
                ull wpk = pk2(w, w);
                ull d = add2(xj, nxc);
                ull a = d & 0x7fffffff7fffffffULL;
                ull t = fma2_(C3, a, C2);
                t = fma2_(t, a, C1);
                t = fma2_(t, a, C0);
                ull u = fma2_(K, t & 0x7fffffff7fffffffULL, t);
                accI = fma2_(u, mul2(d, wpk), accI);
            }
            upk2(accI, lo, hi);
            red_add(outr0 + I * 32 + cx, lo);
            red_add(outr1 + I * 32 + cx, hi);
        }
    }
}

extern "C" void kernel_launch(void* const* d_in, const int* in_sizes, int n_in,
                              void* d_out, int out_size) {
    // Identify inputs by element count (robust to ordering):
    // x: 262144, w1: 256, w2: 4, w3: 32640, diff_indices: 8355840 (unused)
    const float* x = nullptr;
    const float* w1 = nullptr;
    const float* w2 = nullptr;
    const float* w3 = nullptr;
    for (int i = 0; i < n_in; i++) {
        switch (in_sizes[i]) {
            case BB * CC:            x  = (const float*)d_in[i]; break;
            case CC:                 w1 = (const float*)d_in[i]; break;
            case 4:                  w2 = (const float*)d_in[i]; break;
            case CC * (CC - 1) / 2:  w3 = (const float*)d_in[i]; break;
            default: break;  // diff_indices not needed
        }
    }

    // Two graph nodes total: zero the output, then one fused kernel.
    cudaMemsetAsync(d_out, 0, (size_t)out_size * sizeof(float));
    dim3 grid(BB / 16, 9);     // 64 row-groups x 9 rounds = 576 blocks (one wave @ 4/SM)
    son_main_kernel<<<grid, 256>>>(x, w1, w2, w3, (float*)d_out);
}

// round 16
// speedup vs baseline: 1.0810x; 1.0327x over previous
#include <cuda_runtime.h>
#include <cstdint>

#define CC 256
#define BB 1024
typedef unsigned long long ull;

// Round-robin tournament over 8 channel-tiles, ordered so I > J on every
// off-diagonal pass (enables coalesced w3 staging: for j in J-tile, c in
// I-tile, always c > j -> e = base(j) + c - j - 1, consecutive in c).
// Rounds 0..6 = perfect matchings (every unordered pair once); 7,8 = diagonal.
__constant__ int c_I[9][4] = {
    {7,6,5,4},{7,2,6,5},{7,3,4,6},{7,4,5,6},{7,5,6,1},{7,6,3,2},{7,5,4,3},
    {0,1,2,3},{4,5,6,7}};
__constant__ int c_J[9][4] = {
    {0,1,2,3},{1,0,3,4},{2,1,0,5},{3,2,1,0},{4,3,2,0},{5,4,0,1},{6,0,1,2},
    {0,1,2,3},{4,5,6,7}};

// ---- packed f32x2 helpers (sm_100a) ----
__device__ __forceinline__ ull pk2(float lo, float hi) {
    ull r;
    asm("mov.b64 %0, {%1, %2};" : "=l"(r) : "f"(lo), "f"(hi));
    return r;
}
__device__ __forceinline__ void upk2(ull v, float& lo, float& hi) {
    asm("mov.b64 {%0, %1}, %2;" : "=f"(lo), "=f"(hi) : "l"(v));
}
__device__ __forceinline__ ull add2(ull a, ull b) {
    ull r;
    asm("add.rn.f32x2 %0, %1, %2;" : "=l"(r) : "l"(a), "l"(b));
    return r;
}
__device__ __forceinline__ ull mul2(ull a, ull b) {
    ull r;
    asm("mul.rn.f32x2 %0, %1, %2;" : "=l"(r) : "l"(a), "l"(b));
    return r;
}
__device__ __forceinline__ ull fma2_(ull a, ull b, ull c) {
    ull r;
    asm("fma.rn.f32x2 %0, %1, %2, %3;" : "=l"(r) : "l"(a), "l"(b), "l"(c));
    return r;
}
__device__ __forceinline__ void red_add(float* p, float v) {
    asm volatile("red.global.add.f32 [%0], %1;" :: "l"(p), "f"(v) : "memory");
}

// v(c,j) = u(|d|)*(x_j-x_c)*W[j,c] is antisymmetric; each unordered pair computed
// once. Row sums -> accI; column sums -> four lane-rotating accumulators
// (shfl-by-4 per 4 steps; acc_r fixed by content-up-by-r). W tiles are built
// pre-rotated in the prologue straight from w3: with I > J the reads are fully
// coalesced and the rotated smem writes are bank-conflict-free (bank = cL).
__global__ __launch_bounds__(256, 4) void son_main_kernel(
    const float* __restrict__ x, const float* __restrict__ w1,
    const float* __restrict__ w2, const float* __restrict__ w3,
    float* __restrict__ out)
{
    __shared__ float  Wr[4][1024];     // 16 KB: Wr[k][s*32+cx], pre-rotated
    __shared__ float2 xd[8][8][64];    // 32 KB: xd[p][T][i] = x-pair for ch T*32+(i&31), dup'd

    const int tid  = threadIdx.x;
    const int wrp  = tid >> 5;         // row-pair within group (0..7)
    const int cx   = tid & 31;
    const int rg   = blockIdx.x;       // 0..63
    const int rnd  = blockIdx.y;       // 0..8
    const int rowb = rg * 16;

    // Stage x rows, duplicated within each 32-channel tile (coalesced reads)
    {
        float w1s = w1[tid];
        int T = tid >> 5, ci = tid & 31;
#pragma unroll
        for (int p = 0; p < 8; p++) {
            float lo = x[(rowb + 2 * p) * CC + tid] * w1s;
            float hi = x[(rowb + 2 * p + 1) * CC + tid] * w1s;
            float2 v = make_float2(lo, hi);
            xd[p][T][ci]      = v;
            xd[p][T][ci + 32] = v;
        }
    }
    // Stage the round's 4 rotated W tiles straight from w3.
    // Entry (jL, cL): j = J*32+jL, c = I*32+cL; Wr[k][((jL-cL)&31)*32 + cL] = W[j][c].
    // Off-diag (I>J): c>j always -> e = j*(511-j)/2 + (c-j-1), consecutive in cL
    // (lanes) -> coalesced LDG; smem dest bank = cL -> conflict-free STS.
#pragma unroll
    for (int k = 0; k < 4; k++) {
        const int I = c_I[rnd][k], J = c_J[rnd][k];
#pragma unroll
        for (int m = 0; m < 4; m++) {
            int entry = tid + m * 256;          // 0..1023
            int jL = entry >> 5;
            int cL = entry & 31;
            int j = J * 32 + jL;
            int c = I * 32 + cL;
            float v = 0.0f;
            if (j != c) {
                int p = j < c ? j : c;
                int q = j < c ? c : j;
                int e = p * (2 * CC - p - 1) / 2 + (q - p - 1);  // np.triu_indices(CC,1)
                v = __ldg(w3 + e);
            }
            Wr[k][((jL - cL) & 31) * 32 + cL] = v;
        }
    }
    __syncthreads();

    const float s0 = 0.505f * w2[0], s1 = 0.505f * w2[1];
    const float s2 = 0.505f * w2[2], s3 = 0.505f * w2[3];
    const ull C0 = pk2(s0, s0), C1 = pk2(s1, s1);
    const ull C2 = pk2(s2, s2), C3 = pk2(s3, s3);
    const float kf = 0.495f / 0.505f;
    const ull K = pk2(kf, kf);

    const bool diag = (rnd >= 7);
    float* outr0 = out + (rowb + 2 * wrp) * CC;
    float* outr1 = outr0 + CC;

#pragma unroll 1
    for (int k = 0; k < 4; k++) {
        const int I = c_I[rnd][k], J = c_J[rnd][k];
        const ull nxc = (*reinterpret_cast<const ull*>(&xd[wrp][I][cx])) ^ 0x8000000080000000ULL;
        const ull*   xb = reinterpret_cast<const ull*>(&xd[wrp][J][cx]);  // xb[s]: immediate
        const float* Wb = &Wr[k][cx];                                     // Wb[s*32]: immediate
        float lo, hi;

        if (!diag) {
            ull accI = 0ULL;
            ull accJ[4] = {0ULL, 0ULL, 0ULL, 0ULL};
#pragma unroll
            for (int g = 0; g < 8; g++) {
#pragma unroll
                for (int r = 0; r < 4; r++) {
                    const int s = 4 * g + r;
                    float w = Wb[s * 32];
                    ull xj  = xb[s];
                    ull wpk = pk2(w, w);
                    ull d = add2(xj, nxc);
                    ull a = d & 0x7fffffff7fffffffULL;
                    ull t = fma2_(C3, a, C2);
                    t = fma2_(t, a, C1);
                    t = fma2_(t, a, C0);
                    ull u = fma2_(K, t & 0x7fffffff7fffffffULL, t);
                    ull m = mul2(d, wpk);
                    accI    = fma2_(u, m, accI);
                    accJ[r] = fma2_(u, m, accJ[r]);
                }
#pragma unroll
                for (int r = 0; r < 4; r++)
                    accJ[r] = __shfl_sync(0xffffffffu, accJ[r], (cx + 4) & 31);
            }
            // fix-ups: acc_r over-rotated by r -> move content up by r
            accJ[1] = __shfl_sync(0xffffffffu, accJ[1], (cx + 31) & 31);
            accJ[2] = __shfl_sync(0xffffffffu, accJ[2], (cx + 30) & 31);
            accJ[3] = __shfl_sync(0xffffffffu, accJ[3], (cx + 29) & 31);

            upk2(accI, lo, hi);
            red_add(outr0 + I * 32 + cx, lo);
            red_add(outr1 + I * 32 + cx, hi);
            ull negJ = add2(add2(accJ[0], accJ[1]), add2(accJ[2], accJ[3]))
                       ^ 0x8000000080000000ULL;                       // v(j,c) = -v(c,j)
            upk2(negJ, lo, hi);
            red_add(outr0 + J * 32 + cx, lo);
            red_add(outr1 + J * 32 + cx, hi);
        } else {
            ull accI = 0ULL;
#pragma unroll
            for (int s = 0; s < 32; s++) {
                float w = Wb[s * 32];
                ull xj  = xb[s];
                ull wpk = pk2(w, w);
                ull d = add2(xj, nxc);
                ull a = d & 0x7fffffff7fffffffULL;
                ull t = fma2_(C3, a, C2);
                t = fma2_(t, a, C1);
                t = fma2_(t, a, C0);
                ull u = fma2_(K, t & 0x7fffffff7fffffffULL, t);
                accI = fma2_(u, mul2(d, wpk), accI);
            }
            upk2(accI, lo, hi);
            red_add(outr0 + I * 32 + cx, lo);
            red_add(outr1 + I * 32 + cx, hi);
        }
    }
}

extern "C" void kernel_launch(void* const* d_in, const int* in_sizes, int n_in,
                              void* d_out, int out_size) {
    // Identify inputs by element count (robust to ordering):
    // x: 262144, w1: 256, w2: 4, w3: 32640, diff_indices: 8355840 (unused)
    const float* x = nullptr;
    const float* w1 = nullptr;
    const float* w2 = nullptr;
    const float* w3 = nullptr;
    for (int i = 0; i < n_in; i++) {
        switch (in_sizes[i]) {
            case BB * CC:            x  = (const float*)d_in[i]; break;
            case CC:                 w1 = (const float*)d_in[i]; break;
            case 4:                  w2 = (const float*)d_in[i]; break;
            case CC * (CC - 1) / 2:  w3 = (const float*)d_in[i]; break;
            default: break;  // diff_indices not needed
        }
    }

    // Two graph nodes total: zero the output, then one fused kernel.
    cudaMemsetAsync(d_out, 0, (size_t)out_size * sizeof(float));
    dim3 grid(BB / 16, 9);     // 64 row-groups x 9 rounds = 576 blocks (one wave @ 4/SM)
    son_main_kernel<<<grid, 256>>>(x, w1, w2, w3, (float*)d_out);
}

// round 17
// speedup vs baseline: 1.1648x; 1.0775x over previous
#include <cuda_runtime.h>
#include <cstdint>

#define CC 256
#define BB 1024
typedef unsigned long long ull;

// Round-robin tournament over 8 channel-tiles, ordered so I > J on every
// off-diagonal pass (coalesced w3 staging). Rounds 0..6 = perfect matchings;
// rounds 7,8 = diagonal tiles.
__constant__ int c_I[9][4] = {
    {7,6,5,4},{7,2,6,5},{7,3,4,6},{7,4,5,6},{7,5,6,1},{7,6,3,2},{7,5,4,3},
    {0,1,2,3},{4,5,6,7}};
__constant__ int c_J[9][4] = {
    {0,1,2,3},{1,0,3,4},{2,1,0,5},{3,2,1,0},{4,3,2,0},{5,4,0,1},{6,0,1,2},
    {0,1,2,3},{4,5,6,7}};

// ---- packed f32x2 helpers (sm_100a) ----
__device__ __forceinline__ ull pk2(float lo, float hi) {
    ull r;
    asm("mov.b64 %0, {%1, %2};" : "=l"(r) : "f"(lo), "f"(hi));
    return r;
}
__device__ __forceinline__ void upk2(ull v, float& lo, float& hi) {
    asm("mov.b64 {%0, %1}, %2;" : "=f"(lo), "=f"(hi) : "l"(v));
}
__device__ __forceinline__ ull add2(ull a, ull b) {
    ull r;
    asm("add.rn.f32x2 %0, %1, %2;" : "=l"(r) : "l"(a), "l"(b));
    return r;
}
__device__ __forceinline__ ull mul2(ull a, ull b) {
    ull r;
    asm("mul.rn.f32x2 %0, %1, %2;" : "=l"(r) : "l"(a), "l"(b));
    return r;
}
__device__ __forceinline__ ull fma2_(ull a, ull b, ull c) {
    ull r;
    asm("fma.rn.f32x2 %0, %1, %2, %3;" : "=l"(r) : "l"(a), "l"(b), "l"(c));
    return r;
}
__device__ __forceinline__ void red_add(float* p, float v) {
    asm volatile("red.global.add.f32 [%0], %1;" :: "l"(p), "f"(v) : "memory");
}

// v(c,j) = u(|d|)*(x_j-x_c)*W[j,c], antisymmetric; each unordered pair computed
// once (row sums accI, column sums via G=2 lane-rotating accJ, shfl-by-2).
// 128-thread blocks: warp w owns row-pairs w and w+4, so each thread gets a
// 128-reg budget (vs 64 at 256 threads) -> deep software pipelining of the
// ~57-cycle step chain, with W-load + pk2 amortized over 2 contributions.
__global__ __launch_bounds__(128, 4) void son_main_kernel(
    const float* __restrict__ x, const float* __restrict__ w1,
    const float* __restrict__ w2, const float* __restrict__ w3,
    float* __restrict__ out)
{
    __shared__ float  Wr[4][1024];     // 16 KB: Wr[k][s*32+cx], pre-rotated
    __shared__ float2 xd[8][8][64];    // 32 KB: xd[p][T][i], x-pair dup'd per tile

    const int tid  = threadIdx.x;      // 0..127
    const int wrp  = tid >> 5;         // 0..3; owns row-pairs wrp and wrp+4
    const int cx   = tid & 31;
    const int rg   = blockIdx.x;       // 0..63
    const int rnd  = blockIdx.y;       // 0..8
    const int rowb = rg * 16;

    // Stage x rows, duplicated within each 32-channel tile (coalesced reads)
#pragma unroll
    for (int m = 0; m < 16; m++) {
        int idx = tid + m * 128;       // 0..2047
        int p = idx >> 8;
        int c = idx & 255;
        float w1s = __ldg(w1 + c);
        float lo = x[(rowb + 2 * p) * CC + c] * w1s;
        float hi = x[(rowb + 2 * p + 1) * CC + c] * w1s;
        float2 v = make_float2(lo, hi);
        int T = c >> 5, ci = c & 31;
        xd[p][T][ci]      = v;
        xd[p][T][ci + 32] = v;
    }
    // Stage the round's 4 rotated W tiles straight from w3 (coalesced: I>J
    // off-diag -> e consecutive in cL; smem dest bank = cL -> conflict-free).
#pragma unroll
    for (int k = 0; k < 4; k++) {
        const int I = c_I[rnd][k], J = c_J[rnd][k];
#pragma unroll
        for (int m = 0; m < 8; m++) {
            int entry = tid + m * 128;          // 0..1023
            int jL = entry >> 5;
            int cL = entry & 31;
            int j = J * 32 + jL;
            int c = I * 32 + cL;
            float v = 0.0f;
            if (j != c) {
                int p = j < c ? j : c;
                int q = j < c ? c : j;
                int e = p * (2 * CC - p - 1) / 2 + (q - p - 1);  // np.triu_indices(CC,1)
                v = __ldg(w3 + e);
            }
            Wr[k][((jL - cL) & 31) * 32 + cL] = v;
        }
    }
    __syncthreads();

    const float s0 = 0.505f * w2[0], s1 = 0.505f * w2[1];
    const float s2 = 0.505f * w2[2], s3 = 0.505f * w2[3];
    const ull C0 = pk2(s0, s0), C1 = pk2(s1, s1);
    const ull C2 = pk2(s2, s2), C3 = pk2(s3, s3);
    const float kf = 0.495f / 0.505f;
    const ull K = pk2(kf, kf);

    const bool diag = (rnd >= 7);
    const int p0 = wrp, p1 = wrp + 4;
    float* o0r0 = out + (rowb + 2 * p0) * CC;     // pair0 rows
    float* o0r1 = o0r0 + CC;
    float* o1r0 = out + (rowb + 2 * p1) * CC;     // pair1 rows
    float* o1r1 = o1r0 + CC;

#pragma unroll 1
    for (int k = 0; k < 4; k++) {
        const int I = c_I[rnd][k], J = c_J[rnd][k];
        const ull nxc0 = (*reinterpret_cast<const ull*>(&xd[p0][I][cx])) ^ 0x8000000080000000ULL;
        const ull nxc1 = (*reinterpret_cast<const ull*>(&xd[p1][I][cx])) ^ 0x8000000080000000ULL;
        const ull* xb0 = reinterpret_cast<const ull*>(&xd[p0][J][cx]);   // xb[s]: immediate
        const ull* xb1 = reinterpret_cast<const ull*>(&xd[p1][J][cx]);
        const float* Wb = &Wr[k][cx];                                    // Wb[s*32]: immediate
        float lo, hi;

        if (!diag) {
            ull accI0 = 0ULL, accI1 = 0ULL;
            ull accJ0[2] = {0ULL, 0ULL}, accJ1[2] = {0ULL, 0ULL};
#pragma unroll
            for (int g = 0; g < 16; g++) {
#pragma unroll
                for (int r = 0; r < 2; r++) {
                    const int s = 2 * g + r;
                    float w = Wb[s * 32];
                    ull wpk = pk2(w, w);               // shared by both pairs
                    // pair 0
                    {
                        ull xj = xb0[s];
                        ull d = add2(xj, nxc0);
                        ull a = d & 0x7fffffff7fffffffULL;
                        ull t = fma2_(C3, a, C2);
                        t = fma2_(t, a, C1);
                        t = fma2_(t, a, C0);
                        ull u = fma2_(K, t & 0x7fffffff7fffffffULL, t);
                        ull m = mul2(d, wpk);
                        accI0     = fma2_(u, m, accI0);
                        accJ0[r]  = fma2_(u, m, accJ0[r]);
                    }
                    // pair 1 (independent chain)
                    {
                        ull xj = xb1[s];
                        ull d = add2(xj, nxc1);
                        ull a = d & 0x7fffffff7fffffffULL;
                        ull t = fma2_(C3, a, C2);
                        t = fma2_(t, a, C1);
                        t = fma2_(t, a, C0);
                        ull u = fma2_(K, t & 0x7fffffff7fffffffULL, t);
                        ull m = mul2(d, wpk);
                        accI1     = fma2_(u, m, accI1);
                        accJ1[r]  = fma2_(u, m, accJ1[r]);
                    }
                }
                accJ0[0] = __shfl_sync(0xffffffffu, accJ0[0], (cx + 2) & 31);
                accJ0[1] = __shfl_sync(0xffffffffu, accJ0[1], (cx + 2) & 31);
                accJ1[0] = __shfl_sync(0xffffffffu, accJ1[0], (cx + 2) & 31);
                accJ1[1] = __shfl_sync(0xffffffffu, accJ1[1], (cx + 2) & 31);
            }
            // odd-step accumulators over-rotated by 1 -> move content up by 1
            accJ0[1] = __shfl_sync(0xffffffffu, accJ0[1], (cx + 31) & 31);
            accJ1[1] = __shfl_sync(0xffffffffu, accJ1[1], (cx + 31) & 31);

            upk2(accI0, lo, hi);
            red_add(o0r0 + I * 32 + cx, lo);
            red_add(o0r1 + I * 32 + cx, hi);
            upk2(accI1, lo, hi);
            red_add(o1r0 + I * 32 + cx, lo);
            red_add(o1r1 + I * 32 + cx, hi);
            ull negJ0 = add2(accJ0[0], accJ0[1]) ^ 0x8000000080000000ULL;
            upk2(negJ0, lo, hi);
            red_add(o0r0 + J * 32 + cx, lo);
            red_add(o0r1 + J * 32 + cx, hi);
            ull negJ1 = add2(accJ1[0], accJ1[1]) ^ 0x8000000080000000ULL;
            upk2(negJ1, lo, hi);
            red_add(o1r0 + J * 32 + cx, lo);
            red_add(o1r1 + J * 32 + cx, hi);
        } else {
            ull accI0 = 0ULL, accI1 = 0ULL;
#pragma unroll
            for (int s = 0; s < 32; s++) {
                float w = Wb[s * 32];
                ull wpk = pk2(w, w);
                {
                    ull xj = xb0[s];
                    ull d = add2(xj, nxc0);
                    ull a = d & 0x7fffffff7fffffffULL;
                    ull t = fma2_(C3, a, C2);
                    t = fma2_(t, a, C1);
                    t = fma2_(t, a, C0);
                    ull u = fma2_(K, t & 0x7fffffff7fffffffULL, t);
                    accI0 = fma2_(u, mul2(d, wpk), accI0);
                }
                {
                    ull xj = xb1[s];
                    ull d = add2(xj, nxc1);
                    ull a = d & 0x7fffffff7fffffffULL;
                    ull t = fma2_(C3, a, C2);
                    t = fma2_(t, a, C1);
                    t = fma2_(t, a, C0);
                    ull u = fma2_(K, t & 0x7fffffff7fffffffULL, t);
                    accI1 = fma2_(u, mul2(d, wpk), accI1);
                }
            }
            upk2(accI0, lo, hi);
            red_add(o0r0 + I * 32 + cx, lo);
            red_add(o0r1 + I * 32 + cx, hi);
            upk2(accI1, lo, hi);
            red_add(o1r0 + I * 32 + cx, lo);
            red_add(o1r1 + I * 32 + cx, hi);
        }
    }
}

extern "C" void kernel_launch(void* const* d_in, const int* in_sizes, int n_in,
                              void* d_out, int out_size) {
    // Identify inputs by element count (robust to ordering):
    // x: 262144, w1: 256, w2: 4, w3: 32640, diff_indices: 8355840 (unused)
    const float* x = nullptr;
    const float* w1 = nullptr;
    const float* w2 = nullptr;
    const float* w3 = nullptr;
    for (int i = 0; i < n_in; i++) {
        switch (in_sizes[i]) {
            case BB * CC:            x  = (const float*)d_in[i]; break;
            case CC:                 w1 = (const float*)d_in[i]; break;
            case 4:                  w2 = (const float*)d_in[i]; break;
            case CC * (CC - 1) / 2:  w3 = (const float*)d_in[i]; break;
            default: break;  // diff_indices not needed
        }
    }

    // Two graph nodes total: zero the output, then one fused kernel.
    cudaMemsetAsync(d_out, 0, (size_t)out_size * sizeof(float));
    dim3 grid(BB / 16, 9);     // 64 row-groups x 9 rounds = 576 blocks (one wave @ 4/SM)
    son_main_kernel<<<grid, 128>>>(x, w1, w2, w3, (float*)d_out);
}